// round 3
// baseline (speedup 1.0000x reference)
#include <cuda_runtime.h>

#define B 8
#define N 8192
#define D_INF 13
#define M 2048
#define K 32
#define NC (B*M)          /* 16384 centers */
#define NPAIR (NC/2)      /* 8192 */

/* output layout (floats): x_out, pos_s, batch_s */
#define X_OFF   0
#define P_OFF   (NC*128)
#define BA_OFF  (P_OFF + NC*3)

/* scratch (device globals; no allocation allowed) */
static __device__ int   g_fps_idx[NC];
static __device__ int   g_nbr[NC*K];
static __device__ int   g_nvalid[NC];
static __device__ float g_px[B*N];
static __device__ float g_py[B*N];
static __device__ float g_pz[B*N];

/* ------------------------------------------------------------------ */
/* AoS -> SoA transpose of pos                                        */
/* ------------------------------------------------------------------ */
__global__ void soa_kernel(const float* __restrict__ pos) {
    int i = blockIdx.x * blockDim.x + threadIdx.x;
    if (i < B*N) {
        g_px[i] = pos[3*i + 0];
        g_py[i] = pos[3*i + 1];
        g_pz[i] = pos[3*i + 2];
    }
}

/* ------------------------------------------------------------------ */
/* Farthest point sampling: one block per batch, 1024 threads,        */
/* 8 points/thread in registers. Bit-exact distance (no FMA fusion),  */
/* argmax with first-index tie-break via packed 64-bit key.           */
/* ------------------------------------------------------------------ */
__global__ void __launch_bounds__(1024) fps_kernel() {
    const int b = blockIdx.x;
    const int t = threadIdx.x;

    __shared__ unsigned long long best[M];   /* one slot per step: no reset races */
    for (int s = t; s < M; s += 1024) best[s] = 0ULL;

    const float* px = g_px + b*N;
    const float* py = g_py + b*N;
    const float* pz = g_pz + b*N;

    float X[8], Y[8], Z[8], D[8];
#pragma unroll
    for (int i = 0; i < 8; i++) {
        int n = t + i*1024;
        X[i] = px[n]; Y[i] = py[n]; Z[i] = pz[n];
        D[i] = 1e10f;
    }

    if (t == 0) g_fps_idx[b*M] = 0;
    int last = 0;
    __syncthreads();

    for (int s = 1; s < M; s++) {
        const float lx = px[last], ly = py[last], lz = pz[last];  /* L1 broadcast */
        float bv = -1.0f; int bi = t;
#pragma unroll
        for (int i = 0; i < 8; i++) {
            /* match jnp: separate mul + left-to-right sum, NO fma */
            float dx = __fadd_rn(X[i], -lx);
            float dy = __fadd_rn(Y[i], -ly);
            float dz = __fadd_rn(Z[i], -lz);
            float d  = __fadd_rn(__fadd_rn(__fmul_rn(dx,dx), __fmul_rn(dy,dy)),
                                 __fmul_rn(dz,dz));
            float m = fminf(D[i], d);
            D[i] = m;
            if (m > bv) { bv = m; bi = t + i*1024; }   /* strict >: keep smallest idx */
        }
        /* dist >= 0 always: float bits are order-preserving. ~idx so that on
           equal dist the SMALLER index produces the LARGER key (jnp.argmax
           returns first occurrence). */
        unsigned long long key =
            ((unsigned long long)__float_as_uint(bv) << 32) |
            (unsigned long long)(0xFFFFFFFFu - (unsigned)bi);
#pragma unroll
        for (int o = 16; o > 0; o >>= 1) {
            unsigned long long other = __shfl_down_sync(0xFFFFFFFFu, key, o);
            if (other > key) key = other;
        }
        if ((t & 31) == 0) atomicMax(&best[s], key);
        __syncthreads();
        unsigned long long win = best[s];
        last = (int)(0xFFFFFFFFu - (unsigned)(win & 0xFFFFFFFFull));
        if (t == 0) g_fps_idx[b*M + s] = last;
    }
}

/* ------------------------------------------------------------------ */
/* Ball query: one warp per center. First K in-ball points by index   */
/* via ballot + prefix popcount, early exit. Also emits pos_s/batch_s.*/
/* ------------------------------------------------------------------ */
__global__ void __launch_bounds__(256) ballquery_kernel(float* __restrict__ out) {
    const int w    = (blockIdx.x * 256 + threadIdx.x) >> 5;
    const int lane = threadIdx.x & 31;
    if (w >= NC) return;
    const int b = w >> 11;                 /* M = 2048 */

    const float* px = g_px + b*N;
    const float* py = g_py + b*N;
    const float* pz = g_pz + b*N;

    const int ci = g_fps_idx[w];
    const float cx = px[ci], cy = py[ci], cz = pz[ci];

    if (lane == 0) {
        out[P_OFF + 3*w + 0] = cx;
        out[P_OFF + 3*w + 1] = cy;
        out[P_OFF + 3*w + 2] = cz;
        out[BA_OFF + w]      = (float)b;   /* batch[b,n] == b */
    }

    int* nb = g_nbr + w*K;
    int cnt = 0;
    for (int base = 0; base < N; base += 32) {
        int n = base + lane;
        float dx = __fadd_rn(px[n], -cx);
        float dy = __fadd_rn(py[n], -cy);
        float dz = __fadd_rn(pz[n], -cz);
        float d  = __fadd_rn(__fadd_rn(__fmul_rn(dx,dx), __fmul_rn(dy,dy)),
                             __fmul_rn(dz,dz));
        bool in = (d <= 0.04f);            /* float32(0.04) == jnp's R*R cast  */
        unsigned msk = __ballot_sync(0xFFFFFFFFu, in);
        if (in) {
            int slot = cnt + __popc(msk & ((1u << lane) - 1u));
            if (slot < K) nb[slot] = n;
        }
        cnt += __popc(msk);
        if (cnt >= K) break;
    }
    int nv = cnt < K ? cnt : K;            /* >=1: center is in its own ball */
    for (int s2 = nv + lane; s2 < K; s2 += 32) nb[s2] = 0;  /* safe gather idx */
    if (lane == 0) g_nvalid[w] = nv;
}

/* ------------------------------------------------------------------ */
/* Fused gather + MLP(16->64->128) + masked max.                       */
/* Block = 128 threads handles 2 centers per iteration.               */
/*   warps 0,1 -> center g=0 ; warps 2,3 -> center g=1                */
/*   thread owns 2 output channels (W2 columns live in 128 registers) */
/*   h[32][64] per center lives in shared (broadcast LDS.128 reads)   */
/* Grid-stride so W2 register preload amortizes over many centers.    */
/* ------------------------------------------------------------------ */
__global__ void __launch_bounds__(128, 2) mlp_kernel(
    const float* __restrict__ x,
    const float* __restrict__ W1, const float* __restrict__ b1,
    const float* __restrict__ W2, const float* __restrict__ b2,
    float* __restrict__ out)
{
    __shared__ float sW1[16][64];
    __shared__ float sb1[64];
    __shared__ float sh[2][32][68];        /* padded rows, 16B-aligned */
    __shared__ int   s_nv[2];
    __shared__ int   s_nbr[2][32];
    __shared__ float s_cpos[2][3];

    const int t    = threadIdx.x;
    const int g    = t >> 6;               /* which center of the pair   */
    const int tp   = t & 63;               /* channel-pair id (0..63)    */
    const int kk   = (t >> 1) & 31;        /* neighbor for layer 1       */
    const int half = t & 1;                /* 32-channel half in layer 1 */

    for (int i = t; i < 16*64; i += 128) sW1[i >> 6][i & 63] = W1[i];
    if (t < 64) sb1[t] = b1[t];

    float2 w2r[64];
#pragma unroll
    for (int j = 0; j < 64; j++)
        w2r[j] = *(const float2*)(W2 + j*128 + tp*2);
    const float2 b2v = *(const float2*)(b2 + tp*2);

    for (int pair = blockIdx.x; pair < NPAIR; pair += gridDim.x) {
        const int c = pair*2 + g;
        const int b = c >> 11;

        __syncthreads();                   /* protect sh/s_* reuse */
        if (t < 2) {
            int cc = pair*2 + t;
            s_nv[t] = g_nvalid[cc];
            int ci  = g_fps_idx[cc];
            int bb  = cc >> 11;
            s_cpos[t][0] = g_px[bb*N + ci];
            s_cpos[t][1] = g_py[bb*N + ci];
            s_cpos[t][2] = g_pz[bb*N + ci];
        }
        if (t < 64) {
            int cc = pair*2 + (t >> 5);
            s_nbr[t >> 5][t & 31] = g_nbr[cc*K + (t & 31)];
        }
        __syncthreads();

        /* ---------- layer 1: feat(16) @ W1 -> relu -> sh ---------- */
        const int n  = s_nbr[g][kk];
        const int bn = b*N + n;
        float feat[16];
        const float* xr = x + (size_t)bn * D_INF;
#pragma unroll
        for (int j = 0; j < D_INF; j++) feat[j] = xr[j];
        feat[13] = g_px[bn] - s_cpos[g][0];
        feat[14] = g_py[bn] - s_cpos[g][1];
        feat[15] = g_pz[bn] - s_cpos[g][2];

#pragma unroll
        for (int ph = 0; ph < 2; ph++) {
            const int cbase = half*32 + ph*16;
            float hacc[16];
#pragma unroll
            for (int c2 = 0; c2 < 16; c2++) hacc[c2] = sb1[cbase + c2];
#pragma unroll
            for (int j = 0; j < 16; j++) {
                float f = feat[j];
#pragma unroll
                for (int c2 = 0; c2 < 16; c2++)
                    hacc[c2] = fmaf(f, sW1[j][cbase + c2], hacc[c2]);
            }
#pragma unroll
            for (int c2 = 0; c2 < 16; c2 += 4) {
                float4 v;
                v.x = fmaxf(hacc[c2+0], 0.f);
                v.y = fmaxf(hacc[c2+1], 0.f);
                v.z = fmaxf(hacc[c2+2], 0.f);
                v.w = fmaxf(hacc[c2+3], 0.f);
                *(float4*)&sh[g][kk][cbase + c2] = v;
            }
        }
        __syncthreads();

        /* ---------- layer 2: h @ W2 -> max over valid k -> relu ---- */
        const int nv = s_nv[g];
        float m0 = -3.4e38f, m1 = -3.4e38f;
        for (int k = 0; k < nv; k++) {
            const float* hr = sh[g][k];
            float d0a = 0.f, d0b = 0.f, d1a = 0.f, d1b = 0.f;
#pragma unroll
            for (int j = 0; j < 64; j += 4) {
                float4 hv = *(const float4*)(hr + j);
                d0a = fmaf(hv.x, w2r[j+0].x, d0a); d1a = fmaf(hv.x, w2r[j+0].y, d1a);
                d0b = fmaf(hv.y, w2r[j+1].x, d0b); d1b = fmaf(hv.y, w2r[j+1].y, d1b);
                d0a = fmaf(hv.z, w2r[j+2].x, d0a); d1a = fmaf(hv.z, w2r[j+2].y, d1a);
                d0b = fmaf(hv.w, w2r[j+3].x, d0b); d1b = fmaf(hv.w, w2r[j+3].y, d1b);
            }
            m0 = fmaxf(m0, d0a + d0b);
            m1 = fmaxf(m1, d1a + d1b);
        }
        /* relu(max_k(dot)+b2) == max_k(relu(dot+b2)) since relu monotone,
           and at least one valid neighbor always exists */
        float2 o;
        o.x = fmaxf(m0 + b2v.x, 0.f);
        o.y = fmaxf(m1 + b2v.y, 0.f);
        *(float2*)(out + X_OFF + (size_t)c*128 + tp*2) = o;
    }
}

/* ------------------------------------------------------------------ */
extern "C" void kernel_launch(void* const* d_in, const int* in_sizes, int n_in,
                              void* d_out, int out_size) {
    const float* x   = (const float*)d_in[0];
    const float* pos = (const float*)d_in[1];
    /* d_in[2] = batch (int32), values are just the batch index: unused */
    const float* W1  = (const float*)d_in[3];
    const float* b1  = (const float*)d_in[4];
    const float* W2  = (const float*)d_in[5];
    const float* b2  = (const float*)d_in[6];
    float* out = (float*)d_out;

    soa_kernel<<<(B*N + 255)/256, 256>>>(pos);
    fps_kernel<<<B, 1024>>>();
    ballquery_kernel<<<(NC*32)/256, 256>>>(out);
    mlp_kernel<<<304, 128>>>(x, W1, b1, W2, b2, out);
}

// round 4
// speedup vs baseline: 1.5938x; 1.5938x over previous
#include <cuda_runtime.h>

#define B 8
#define N 8192
#define D_INF 13
#define M 2048
#define K 32
#define NC (B*M)          /* 16384 centers */
#define NPAIR (NC/2)      /* 8192 */

/* output layout (floats): x_out, pos_s, batch_s */
#define X_OFF   0
#define P_OFF   (NC*128)
#define BA_OFF  (P_OFF + NC*3)

/* scratch (device globals; no allocation allowed) */
static __device__ int   g_fps_idx[NC];
static __device__ int   g_nbr[NC*K];
static __device__ int   g_nvalid[NC];
static __device__ float g_px[B*N];
static __device__ float g_py[B*N];
static __device__ float g_pz[B*N];

/* ---------------- packed f32x2 helpers (per-lane IEEE RN, bit-exact) ---- */
union F2U { unsigned long long u; float2 f; };

__device__ __forceinline__ unsigned long long pk2(float lo, float hi) {
    F2U c; c.f = make_float2(lo, hi); return c.u;
}
__device__ __forceinline__ float2 up2(unsigned long long v) {
    F2U c; c.u = v; return c.f;
}
__device__ __forceinline__ unsigned long long add2(unsigned long long a,
                                                   unsigned long long b) {
    unsigned long long r;
    asm("add.rn.f32x2 %0, %1, %2;" : "=l"(r) : "l"(a), "l"(b));
    return r;
}
__device__ __forceinline__ unsigned long long mul2(unsigned long long a,
                                                   unsigned long long b) {
    unsigned long long r;
    asm("mul.rn.f32x2 %0, %1, %2;" : "=l"(r) : "l"(a), "l"(b));
    return r;
}

/* ------------------------------------------------------------------ */
/* AoS -> SoA transpose of pos                                        */
/* ------------------------------------------------------------------ */
__global__ void soa_kernel(const float* __restrict__ pos) {
    int i = blockIdx.x * blockDim.x + threadIdx.x;
    if (i < B*N) {
        g_px[i] = pos[3*i + 0];
        g_py[i] = pos[3*i + 1];
        g_pz[i] = pos[3*i + 2];
    }
}

/* ------------------------------------------------------------------ */
/* Farthest point sampling v2: one block per batch, 512 threads,      */
/* 16 points/thread in packed f32x2 registers.                        */
/*  - distances via add.rn.f32x2/mul.rn.f32x2 (bit-exact per lane,    */
/*    matches jnp's (dx^2+dy^2)+dz^2 with no FMA contraction)         */
/*  - argmax: REDUX warp max -> 16 shared keys -> REDUX block max,    */
/*    then only matching warps recover the min index via atomicMin    */
/*    (float bits of nonneg dists are order-preserving as u32)        */
/*  - 2 barriers/step, no serialized same-address atomic chain        */
/* ------------------------------------------------------------------ */
#define FPS_T 512
#define FPS_W (FPS_T/32)

__global__ void __launch_bounds__(FPS_T, 1) fps_kernel() {
    const int b    = blockIdx.x;
    const int t    = threadIdx.x;
    const int w    = t >> 5;
    const int lane = t & 31;

    __shared__ unsigned skey[FPS_W];
    __shared__ int      swidx[2];

    const float* px = g_px + b*N;
    const float* py = g_py + b*N;
    const float* pz = g_pz + b*N;

    unsigned long long X[8], Y[8], Z[8];
    float D[16];
#pragma unroll
    for (int j = 0; j < 8; j++) {
        int n0 = t + 512*(2*j), n1 = n0 + 512;
        X[j] = pk2(px[n0], px[n1]);
        Y[j] = pk2(py[n0], py[n1]);
        Z[j] = pk2(pz[n0], pz[n1]);
        D[2*j] = 1e10f; D[2*j+1] = 1e10f;
    }
    if (t == 0) {
        g_fps_idx[b*M] = 0;
        swidx[0] = 0x7fffffff;
        swidx[1] = 0x7fffffff;
    }
    int last = 0;
    __syncthreads();

    for (int s = 1; s < M; s++) {
        const int p = s & 1;
        const float lx = px[last], ly = py[last], lz = pz[last];
        const unsigned long long nx = pk2(-lx, -lx);
        const unsigned long long ny = pk2(-ly, -ly);
        const unsigned long long nz = pk2(-lz, -lz);

        float bv = -1.0f;
#pragma unroll
        for (int j = 0; j < 8; j++) {
            unsigned long long dx = add2(X[j], nx);
            unsigned long long dy = add2(Y[j], ny);
            unsigned long long dz = add2(Z[j], nz);
            unsigned long long d2 = add2(add2(mul2(dx,dx), mul2(dy,dy)),
                                         mul2(dz,dz));
            float2 dd = up2(d2);
            float a = fminf(D[2*j],   dd.x);
            float c = fminf(D[2*j+1], dd.y);
            D[2*j] = a; D[2*j+1] = c;
            bv = fmaxf(bv, fmaxf(a, c));
        }

        const unsigned bvb = __float_as_uint(bv);            /* dist>=0 */
        const unsigned wvb = __reduce_max_sync(0xffffffffu, bvb);
        if (lane == 0) skey[w] = wvb;
        __syncthreads();                                     /* bar 1 */

        if (t == 0) swidx[p ^ 1] = 0x7fffffff;               /* for step s+1 */

        unsigned v = (lane < FPS_W) ? skey[lane] : 0u;
        const unsigned winb = __reduce_max_sync(0xffffffffu, v);

        if (bvb == winb) {                                   /* rare path */
            const float wf = __uint_as_float(winb);
            int cand = 0x7fffffff;
#pragma unroll
            for (int i = 15; i >= 0; i--)
                if (D[i] == wf) cand = t + 512*i;            /* first i wins */
            atomicMin(&swidx[p], cand);                      /* min global idx */
        }
        __syncthreads();                                     /* bar 2 */

        last = swidx[p];
        if (t == 0) g_fps_idx[b*M + s] = last;
    }
}

/* ------------------------------------------------------------------ */
/* Ball query: one warp per center. First K in-ball points by index   */
/* via ballot + prefix popcount, early exit. Also emits pos_s/batch_s.*/
/* ------------------------------------------------------------------ */
__global__ void __launch_bounds__(256) ballquery_kernel(float* __restrict__ out) {
    const int w    = (blockIdx.x * 256 + threadIdx.x) >> 5;
    const int lane = threadIdx.x & 31;
    if (w >= NC) return;
    const int b = w >> 11;                 /* M = 2048 */

    const float* px = g_px + b*N;
    const float* py = g_py + b*N;
    const float* pz = g_pz + b*N;

    const int ci = g_fps_idx[w];
    const float cx = px[ci], cy = py[ci], cz = pz[ci];

    if (lane == 0) {
        out[P_OFF + 3*w + 0] = cx;
        out[P_OFF + 3*w + 1] = cy;
        out[P_OFF + 3*w + 2] = cz;
        out[BA_OFF + w]      = (float)b;   /* batch[b,n] == b */
    }

    int* nb = g_nbr + w*K;
    int cnt = 0;
    for (int base = 0; base < N; base += 32) {
        int n = base + lane;
        float dx = __fadd_rn(px[n], -cx);
        float dy = __fadd_rn(py[n], -cy);
        float dz = __fadd_rn(pz[n], -cz);
        float d  = __fadd_rn(__fadd_rn(__fmul_rn(dx,dx), __fmul_rn(dy,dy)),
                             __fmul_rn(dz,dz));
        bool in = (d <= 0.04f);            /* float32(0.04) == jnp's R*R cast  */
        unsigned msk = __ballot_sync(0xFFFFFFFFu, in);
        if (in) {
            int slot = cnt + __popc(msk & ((1u << lane) - 1u));
            if (slot < K) nb[slot] = n;
        }
        cnt += __popc(msk);
        if (cnt >= K) break;
    }
    int nv = cnt < K ? cnt : K;            /* >=1: center is in its own ball */
    for (int s2 = nv + lane; s2 < K; s2 += 32) nb[s2] = 0;  /* safe gather idx */
    if (lane == 0) g_nvalid[w] = nv;
}

/* ------------------------------------------------------------------ */
/* Fused gather + MLP(16->64->128) + masked max.                       */
/* Block = 128 threads handles 2 centers per iteration.               */
/*   warps 0,1 -> center g=0 ; warps 2,3 -> center g=1                */
/*   thread owns 2 output channels (W2 columns live in 128 registers) */
/*   h[32][64] per center lives in shared (broadcast LDS.128 reads)   */
/* Grid-stride so W2 register preload amortizes over many centers.    */
/* ------------------------------------------------------------------ */
__global__ void __launch_bounds__(128, 2) mlp_kernel(
    const float* __restrict__ x,
    const float* __restrict__ W1, const float* __restrict__ b1,
    const float* __restrict__ W2, const float* __restrict__ b2,
    float* __restrict__ out)
{
    __shared__ float sW1[16][64];
    __shared__ float sb1[64];
    __shared__ float sh[2][32][68];        /* padded rows, 16B-aligned */
    __shared__ int   s_nv[2];
    __shared__ int   s_nbr[2][32];
    __shared__ float s_cpos[2][3];

    const int t    = threadIdx.x;
    const int g    = t >> 6;               /* which center of the pair   */
    const int tp   = t & 63;               /* channel-pair id (0..63)    */
    const int kk   = (t >> 1) & 31;        /* neighbor for layer 1       */
    const int half = t & 1;                /* 32-channel half in layer 1 */

    for (int i = t; i < 16*64; i += 128) sW1[i >> 6][i & 63] = W1[i];
    if (t < 64) sb1[t] = b1[t];

    float2 w2r[64];
#pragma unroll
    for (int j = 0; j < 64; j++)
        w2r[j] = *(const float2*)(W2 + j*128 + tp*2);
    const float2 b2v = *(const float2*)(b2 + tp*2);

    for (int pair = blockIdx.x; pair < NPAIR; pair += gridDim.x) {
        const int c = pair*2 + g;
        const int b = c >> 11;

        __syncthreads();                   /* protect sh/s_* reuse */
        if (t < 2) {
            int cc = pair*2 + t;
            s_nv[t] = g_nvalid[cc];
            int ci  = g_fps_idx[cc];
            int bb  = cc >> 11;
            s_cpos[t][0] = g_px[bb*N + ci];
            s_cpos[t][1] = g_py[bb*N + ci];
            s_cpos[t][2] = g_pz[bb*N + ci];
        }
        if (t < 64) {
            int cc = pair*2 + (t >> 5);
            s_nbr[t >> 5][t & 31] = g_nbr[cc*K + (t & 31)];
        }
        __syncthreads();

        /* ---------- layer 1: feat(16) @ W1 -> relu -> sh ---------- */
        const int n  = s_nbr[g][kk];
        const int bn = b*N + n;
        float feat[16];
        const float* xr = x + (size_t)bn * D_INF;
#pragma unroll
        for (int j = 0; j < D_INF; j++) feat[j] = xr[j];
        feat[13] = g_px[bn] - s_cpos[g][0];
        feat[14] = g_py[bn] - s_cpos[g][1];
        feat[15] = g_pz[bn] - s_cpos[g][2];

#pragma unroll
        for (int ph = 0; ph < 2; ph++) {
            const int cbase = half*32 + ph*16;
            float hacc[16];
#pragma unroll
            for (int c2 = 0; c2 < 16; c2++) hacc[c2] = sb1[cbase + c2];
#pragma unroll
            for (int j = 0; j < 16; j++) {
                float f = feat[j];
#pragma unroll
                for (int c2 = 0; c2 < 16; c2++)
                    hacc[c2] = fmaf(f, sW1[j][cbase + c2], hacc[c2]);
            }
#pragma unroll
            for (int c2 = 0; c2 < 16; c2 += 4) {
                float4 v;
                v.x = fmaxf(hacc[c2+0], 0.f);
                v.y = fmaxf(hacc[c2+1], 0.f);
                v.z = fmaxf(hacc[c2+2], 0.f);
                v.w = fmaxf(hacc[c2+3], 0.f);
                *(float4*)&sh[g][kk][cbase + c2] = v;
            }
        }
        __syncthreads();

        /* ---------- layer 2: h @ W2 -> max over valid k -> relu ---- */
        const int nv = s_nv[g];
        float m0 = -3.4e38f, m1 = -3.4e38f;
        for (int k = 0; k < nv; k++) {
            const float* hr = sh[g][k];
            float d0a = 0.f, d0b = 0.f, d1a = 0.f, d1b = 0.f;
#pragma unroll
            for (int j = 0; j < 64; j += 4) {
                float4 hv = *(const float4*)(hr + j);
                d0a = fmaf(hv.x, w2r[j+0].x, d0a); d1a = fmaf(hv.x, w2r[j+0].y, d1a);
                d0b = fmaf(hv.y, w2r[j+1].x, d0b); d1b = fmaf(hv.y, w2r[j+1].y, d1b);
                d0a = fmaf(hv.z, w2r[j+2].x, d0a); d1a = fmaf(hv.z, w2r[j+2].y, d1a);
                d0b = fmaf(hv.w, w2r[j+3].x, d0b); d1b = fmaf(hv.w, w2r[j+3].y, d1b);
            }
            m0 = fmaxf(m0, d0a + d0b);
            m1 = fmaxf(m1, d1a + d1b);
        }
        /* relu(max_k(dot)+b2) == max_k(relu(dot+b2)) since relu monotone,
           and at least one valid neighbor always exists */
        float2 o;
        o.x = fmaxf(m0 + b2v.x, 0.f);
        o.y = fmaxf(m1 + b2v.y, 0.f);
        *(float2*)(out + X_OFF + (size_t)c*128 + tp*2) = o;
    }
}

/* ------------------------------------------------------------------ */
extern "C" void kernel_launch(void* const* d_in, const int* in_sizes, int n_in,
                              void* d_out, int out_size) {
    const float* x   = (const float*)d_in[0];
    const float* pos = (const float*)d_in[1];
    /* d_in[2] = batch (int32), values are just the batch index: unused */
    const float* W1  = (const float*)d_in[3];
    const float* b1  = (const float*)d_in[4];
    const float* W2  = (const float*)d_in[5];
    const float* b2  = (const float*)d_in[6];
    float* out = (float*)d_out;

    soa_kernel<<<(B*N + 255)/256, 256>>>(pos);
    fps_kernel<<<B, FPS_T>>>();
    ballquery_kernel<<<(NC*32)/256, 256>>>(out);
    mlp_kernel<<<304, 128>>>(x, W1, b1, W2, b2, out);
}